// round 1
// baseline (speedup 1.0000x reference)
#include <cuda_runtime.h>
#include <cstdint>

#define B_TOTAL 16384
#define NN 64
#define DD 64

// Scratch for precomputed user-embedding contribution: UEP[b][j] = ue[b]@W1[0:64] + b1
__device__ float g_uep[B_TOTAL * DD];

__device__ __forceinline__ uint32_t f2tf32(float x) {
    uint32_t r;
    asm("cvt.rna.tf32.f32 %0, %1;" : "=r"(r) : "f"(x));
    return r;
}

// ---------------------------------------------------------------------------
// Kernel 1: UEP[b][j] = b1[j] + sum_k ue[b][k] * W1[k][j]   (upper half of W1)
// ---------------------------------------------------------------------------
__global__ __launch_bounds__(256) void uep_kernel(const float* __restrict__ ue,
                                                  const float* __restrict__ W1,
                                                  const float* __restrict__ b1) {
    int b = blockIdx.x * 4 + (threadIdx.x >> 6);
    int j = threadIdx.x & 63;
    const float* u = ue + (size_t)b * 64;
    float acc = b1[j];
#pragma unroll 8
    for (int k = 0; k < 64; k++)
        acc = fmaf(u[k], W1[k * 64 + j], acc);
    g_uep[(size_t)b * 64 + j] = acc;
}

// ---------------------------------------------------------------------------
// Kernel 2: per batch b:
//   H^T[j][n] = sum_k W1[64+k][j] * rel[b][n][k]           (tf32 mma, W^T as A)
//   score[n]  = sum_j relu(H[j][n] + UEP[b][j]) * w2[j]
//   decay     = softmax_n(sigmoid(score + b2))
//   out[b]    = [ self[b] , sum_n decay[n]*nv[b][n][:] ]
// ---------------------------------------------------------------------------
__global__ __launch_bounds__(128, 4) void agg_kernel(
    const float* __restrict__ self_v,
    const float* __restrict__ nv,
    const float* __restrict__ rel,
    const float* __restrict__ W1,
    const float* __restrict__ w2,
    const float* __restrict__ b2,
    float* __restrict__ out)
{
    // rel tile staged as tf32, k-permuted so (k, k+4) are adjacent words.
    // Row stride 68 words -> LDS.64 B-fragment reads are conflict-free.
    __shared__ __align__(16) uint32_t sA[64 * 68];
    __shared__ float sUEp[64];
    __shared__ float sW2[64];
    __shared__ float sE[64];
    __shared__ float sRed[256];
    __shared__ float sInv;

    const int tid  = threadIdx.x;
    const int warp = tid >> 5;
    const int lane = tid & 31;
    const int g = lane >> 2;   // groupID
    const int q = lane & 3;    // threadID_in_group
    const int j0 = warp * 16;  // each warp owns 16 j-rows of H^T

    // A operand = W1_lower^T (j x k), batch-invariant: load into regs once.
    // m16n8k8 A frag (row-major): a0=(g,q) a1=(g+8,q) a2=(g,q+4) a3=(g+8,q+4)
    uint32_t aW[8][4];
#pragma unroll
    for (int ks = 0; ks < 8; ks++) {
        int k0 = ks * 8 + q;
        aW[ks][0] = f2tf32(W1[(64 + k0)     * 64 + j0 + g]);
        aW[ks][1] = f2tf32(W1[(64 + k0)     * 64 + j0 + g + 8]);
        aW[ks][2] = f2tf32(W1[(64 + k0 + 4) * 64 + j0 + g]);
        aW[ks][3] = f2tf32(W1[(64 + k0 + 4) * 64 + j0 + g + 8]);
    }
    if (tid < 64) sW2[tid] = w2[tid];
    const float b2v = b2[0];

    for (int bi = 0; bi < 8; bi++) {
        const int b = blockIdx.x * 8 + bi;

        // ---- stage rel[b] -> smem (tf32, permuted) ----
        const float4* relv = reinterpret_cast<const float4*>(rel + (size_t)b * 4096);
#pragma unroll
        for (int i = tid; i < 1024; i += 128) {
            float4 v = relv[i];
            int n = i >> 4;            // 16 float4 per 64-wide row
            int k = (i & 15) << 2;     // k base, multiple of 4
            // permuted index within row: (k>>3)*8 + (k&3)*2 + ((k>>2)&1)
            uint32_t* p = &sA[n * 68 + ((k >> 3) << 3) + ((k >> 2) & 1)];
            p[0] = f2tf32(v.x); p[2] = f2tf32(v.y);
            p[4] = f2tf32(v.z); p[6] = f2tf32(v.w);
        }
        if (tid < 64) sUEp[tid] = g_uep[(size_t)b * 64 + tid];
        __syncthreads();

        // ---- GEMM: H^T[j0..j0+15][0..63] per warp ----
        float c[8][4];
#pragma unroll
        for (int nt = 0; nt < 8; nt++)
            c[nt][0] = c[nt][1] = c[nt][2] = c[nt][3] = 0.f;

#pragma unroll
        for (int ks = 0; ks < 8; ks++) {
#pragma unroll
            for (int nt = 0; nt < 8; nt++) {
                // B frag (col-major k x n): b0=(q, g), b1=(q+4, g) within tile
                uint2 bv = *reinterpret_cast<const uint2*>(
                    &sA[(nt * 8 + g) * 68 + ks * 8 + 2 * q]);
                asm volatile(
                    "mma.sync.aligned.m16n8k8.row.col.f32.tf32.tf32.f32 "
                    "{%0,%1,%2,%3}, {%4,%5,%6,%7}, {%8,%9}, {%0,%1,%2,%3};\n"
                    : "+f"(c[nt][0]), "+f"(c[nt][1]), "+f"(c[nt][2]), "+f"(c[nt][3])
                    : "r"(aW[ks][0]), "r"(aW[ks][1]), "r"(aW[ks][2]), "r"(aW[ks][3]),
                      "r"(bv.x), "r"(bv.y));
            }
        }

        // ---- epilogue: relu(+UEP)*w2, reduce over j ----
        // C frag: c0=(j0+g, 2q) c1=(j0+g, 2q+1) c2=(j0+g+8, 2q) c3=(j0+g+8, 2q+1)
        {
            float ue0 = sUEp[j0 + g],     ue1 = sUEp[j0 + g + 8];
            float w20 = sW2[j0 + g],      w21 = sW2[j0 + g + 8];
#pragma unroll
            for (int nt = 0; nt < 8; nt++) {
                float p0 = fmaxf(c[nt][0] + ue0, 0.f) * w20
                         + fmaxf(c[nt][2] + ue1, 0.f) * w21;   // n = nt*8 + 2q
                float p1 = fmaxf(c[nt][1] + ue0, 0.f) * w20
                         + fmaxf(c[nt][3] + ue1, 0.f) * w21;   // n = nt*8 + 2q + 1
#pragma unroll
                for (int d = 4; d < 32; d <<= 1) {
                    p0 += __shfl_xor_sync(0xffffffffu, p0, d);
                    p1 += __shfl_xor_sync(0xffffffffu, p1, d);
                }
                if (lane < 4) {
                    sRed[warp * 64 + nt * 8 + 2 * q]     = p0;
                    sRed[warp * 64 + nt * 8 + 2 * q + 1] = p1;
                }
            }
        }
        __syncthreads();

        // ---- sigmoid + exp (softmax numerator; logits in (0,1), no max needed) ----
        if (tid < 64) {
            float s = sRed[tid] + sRed[64 + tid] + sRed[128 + tid] + sRed[192 + tid] + b2v;
            float l = 1.f / (1.f + __expf(-s));
            sE[tid] = __expf(l);
        }
        __syncthreads();
        if (tid < 32) {
            float v = sE[tid] + sE[tid + 32];
#pragma unroll
            for (int d = 16; d > 0; d >>= 1)
                v += __shfl_xor_sync(0xffffffffu, v, d);
            if (tid == 0) sInv = 1.f / v;
        }
        __syncthreads();

        // ---- agg: sum_n decay[n] * nv[b][n][:]  (coalesced 128B rows) ----
        {
            int d = tid & 63, half = tid >> 6;
            const float* nvb = nv + (size_t)b * 4096 + half * 2048 + d;
            float acc = 0.f;
#pragma unroll
            for (int n = 0; n < 32; n++)
                acc = fmaf(sE[half * 32 + n], nvb[n * 64], acc);
            sRed[half * 64 + d] = acc;
        }
        __syncthreads();

        if (tid < 64) {
            out[(size_t)b * 128 + tid]      = self_v[(size_t)b * 64 + tid];
            out[(size_t)b * 128 + 64 + tid] = (sRed[tid] + sRed[64 + tid]) * sInv;
        }
        __syncthreads();
    }
}

extern "C" void kernel_launch(void* const* d_in, const int* in_sizes, int n_in,
                              void* d_out, int out_size) {
    const float* self_v = (const float*)d_in[0];
    const float* nv     = (const float*)d_in[1];
    const float* rel    = (const float*)d_in[2];
    const float* ue     = (const float*)d_in[3];
    const float* W1     = (const float*)d_in[4];
    const float* b1     = (const float*)d_in[5];
    const float* w2     = (const float*)d_in[6];
    const float* b2     = (const float*)d_in[7];
    float* out = (float*)d_out;

    uep_kernel<<<B_TOTAL / 4, 256>>>(ue, W1, b1);
    agg_kernel<<<B_TOTAL / 8, 128>>>(self_v, nv, rel, W1, w2, b2, out);
}

// round 2
// speedup vs baseline: 1.0561x; 1.0561x over previous
#include <cuda_runtime.h>
#include <cstdint>

#define B_TOTAL 16384

// ---------------- smem layout (dynamic, floats) ----------------
// sRel : 2 * 64*68      = 8704   (rel double buffer, stride-68 rows, raw fp32 bits)
// sNv  : 64*64          = 4096   (nv prefetch buffer)
// sUEp : 64
// sW2  : 64
// sE   : 64
// sRed : 256
#define OFF_REL  0
#define OFF_NV   8704
#define OFF_UEP  12800
#define OFF_W2   12864
#define OFF_E    12928
#define OFF_RED  12992
#define SMEM_FLOATS 13248
#define SMEM_BYTES  (SMEM_FLOATS * 4)

__device__ __forceinline__ uint32_t f2tf32(float x) {
    uint32_t r;
    asm("cvt.rna.tf32.f32 %0, %1;" : "=r"(r) : "f"(x));
    return r;
}

__device__ __forceinline__ void cp16(float* s, const float* g) {
    uint32_t sa = (uint32_t)__cvta_generic_to_shared(s);
    asm volatile("cp.async.cg.shared.global [%0], [%1], 16;\n" :: "r"(sa), "l"(g));
}
__device__ __forceinline__ void cp_commit() { asm volatile("cp.async.commit_group;\n"); }
template <int N>
__device__ __forceinline__ void cp_wait() { asm volatile("cp.async.wait_group %0;\n" :: "n"(N)); }

// stage rel[b] -> sRel buffer (row n at stride 68, 16B chunks)
__device__ __forceinline__ void stage_rel(float* dst, const float* __restrict__ rel,
                                          int b, int tid) {
    const float* src = rel + (size_t)b * 4096;
#pragma unroll
    for (int c = 0; c < 8; c++) {
        int i = tid + c * 128;          // chunk id 0..1023
        int n = i >> 4, w = i & 15;
        cp16(dst + n * 68 + w * 4, src + i * 4);
    }
    cp_commit();
}

// stage nv[b] -> sNv (linear)
__device__ __forceinline__ void stage_nv(float* dst, const float* __restrict__ nv,
                                         int b, int tid) {
    const float* src = nv + (size_t)b * 4096;
#pragma unroll
    for (int c = 0; c < 8; c++) {
        int i = tid + c * 128;
        cp16(dst + i * 4, src + i * 4);
    }
    cp_commit();
}

__global__ __launch_bounds__(128, 4) void agg_kernel(
    const float* __restrict__ self_v,
    const float* __restrict__ nv,
    const float* __restrict__ rel,
    const float* __restrict__ ue,
    const float* __restrict__ W1,
    const float* __restrict__ b1,
    const float* __restrict__ w2,
    const float* __restrict__ b2,
    float* __restrict__ out)
{
    extern __shared__ __align__(16) float smem[];
    float* sRel = smem + OFF_REL;
    float* sNv  = smem + OFF_NV;
    float* sUEp = smem + OFF_UEP;
    float* sW2  = smem + OFF_W2;
    float* sE   = smem + OFF_E;
    float* sRed = smem + OFF_RED;

    const int tid  = threadIdx.x;
    const int warp = tid >> 5;
    const int lane = tid & 31;
    const int g = lane >> 2;   // groupID
    const int q = lane & 3;    // threadID_in_group
    const int j0 = warp * 16;  // each warp owns 16 j-rows of H^T

    // A operand = W1_lower^T (j x k), batch-invariant, in registers.
    // m16n8k8 A frag (row-major): a0=(g,q) a1=(g+8,q) a2=(g,q+4) a3=(g+8,q+4)
    uint32_t aW[8][4];
#pragma unroll
    for (int ks = 0; ks < 8; ks++) {
        int k0 = ks * 8 + q;
        aW[ks][0] = f2tf32(W1[(64 + k0)     * 64 + j0 + g]);
        aW[ks][1] = f2tf32(W1[(64 + k0)     * 64 + j0 + g + 8]);
        aW[ks][2] = f2tf32(W1[(64 + k0 + 4) * 64 + j0 + g]);
        aW[ks][3] = f2tf32(W1[(64 + k0 + 4) * 64 + j0 + g + 8]);
    }
    if (tid < 64) sW2[tid] = w2[tid];
    const float b2v = b2[0];
    const int b_base = blockIdx.x * 8;

    // ---- pipeline prologue: G0=rel0, G1=nv0, G2=rel1 ----
    stage_rel(sRel,         rel, b_base,     tid);
    stage_nv (sNv,          nv,  b_base,     tid);
    stage_rel(sRel + 4352,  rel, b_base + 1, tid);

#pragma unroll 1
    for (int bi = 0; bi < 8; bi++) {
        const int b = b_base + bi;

        // ---- uep[j] = b1[j] + ue[b] @ W1_upper[:,j]  (overlaps cp.async) ----
        if (tid < 64) {
            float acc = __ldg(b1 + tid);
            const float* u = ue + (size_t)b * 64;
#pragma unroll 8
            for (int k = 0; k < 64; k++)
                acc = fmaf(__ldg(u + k), __ldg(W1 + k * 64 + tid), acc);
            sUEp[tid] = acc;
        }

        // need rel[bi] complete
        if (bi == 7) cp_wait<1>(); else cp_wait<2>();
        __syncthreads();   // A: sRel[buf], sUEp visible

        // ---- GEMM: H^T[j0..j0+15][0..63] per warp (raw-bit tf32) ----
        const float* A = sRel + (bi & 1) * 4352;
        float c[8][4];
#pragma unroll
        for (int nt = 0; nt < 8; nt++)
            c[nt][0] = c[nt][1] = c[nt][2] = c[nt][3] = 0.f;

#pragma unroll
        for (int ks = 0; ks < 8; ks++) {
#pragma unroll
            for (int nt = 0; nt < 8; nt++) {
                // B frag: b0=(k=8ks+q, n), b1=(k=8ks+q+4, n), n = nt*8+g
                const float* row = A + (nt * 8 + g) * 68 + ks * 8;
                uint32_t bv0 = __float_as_uint(row[q]);
                uint32_t bv1 = __float_as_uint(row[q + 4]);
                asm volatile(
                    "mma.sync.aligned.m16n8k8.row.col.f32.tf32.tf32.f32 "
                    "{%0,%1,%2,%3}, {%4,%5,%6,%7}, {%8,%9}, {%0,%1,%2,%3};\n"
                    : "+f"(c[nt][0]), "+f"(c[nt][1]), "+f"(c[nt][2]), "+f"(c[nt][3])
                    : "r"(aW[ks][0]), "r"(aW[ks][1]), "r"(aW[ks][2]), "r"(aW[ks][3]),
                      "r"(bv0), "r"(bv1));
            }
        }

        // ---- epilogue: relu(+UEP)*w2, reduce over this warp's 16 j ----
        // C frag: c0=(j0+g, 2q) c1=(j0+g, 2q+1) c2=(j0+g+8, 2q) c3=(j0+g+8, 2q+1)
        {
            float ue0 = sUEp[j0 + g], ue1 = sUEp[j0 + g + 8];
            float w20 = sW2[j0 + g],  w21 = sW2[j0 + g + 8];
#pragma unroll
            for (int nt = 0; nt < 8; nt++) {
                float p0 = fmaxf(c[nt][0] + ue0, 0.f) * w20
                         + fmaxf(c[nt][2] + ue1, 0.f) * w21;   // n = nt*8 + 2q
                float p1 = fmaxf(c[nt][1] + ue0, 0.f) * w20
                         + fmaxf(c[nt][3] + ue1, 0.f) * w21;   // n = nt*8 + 2q + 1
#pragma unroll
                for (int d = 4; d < 32; d <<= 1) {
                    p0 += __shfl_xor_sync(0xffffffffu, p0, d);
                    p1 += __shfl_xor_sync(0xffffffffu, p1, d);
                }
                if (lane < 4) {
                    sRed[warp * 64 + nt * 8 + 2 * q]     = p0;
                    sRed[warp * 64 + nt * 8 + 2 * q + 1] = p1;
                }
            }
        }
        __syncthreads();   // B: sRed visible; sRel[buf] free

        // ---- sigmoid->exp on warps 0-1; self copy on warps 2-3 ----
        if (tid < 64) {
            float s = sRed[tid] + sRed[64 + tid] + sRed[128 + tid] + sRed[192 + tid] + b2v;
            float l = 1.f / (1.f + __expf(-s));
            sE[tid] = __expf(l);
        } else {
            int i = tid - 64;
            out[(size_t)b * 128 + i] = __ldg(self_v + (size_t)b * 64 + i);
        }

        // need nv[bi] complete
        if (bi == 7) cp_wait<0>(); else cp_wait<1>();
        __syncthreads();   // C: sE, sNv visible

        // ---- agg: out[64+d] = (sum_n e[n]*nv[n][d]) / (sum_n e[n]) ----
        if (tid < 64) {
            float acc = 0.f, te = 0.f;
#pragma unroll
            for (int n = 0; n < 64; n++) {
                float e = sE[n];
                te += e;
                acc = fmaf(e, sNv[n * 64 + tid], acc);
            }
            out[(size_t)b * 128 + 64 + tid] = __fdividef(acc, te);
        }
        __syncthreads();   // E: sNv / sE free for next-iteration prefetch

        // ---- issue next prefetches ----
        if (bi < 7) {
            stage_nv(sNv, nv, b + 1, tid);                       // nv[bi+1]
            if (bi < 6)
                stage_rel(sRel + (bi & 1) * 4352, rel, b + 2, tid);  // rel[bi+2]
        }
    }
}

extern "C" void kernel_launch(void* const* d_in, const int* in_sizes, int n_in,
                              void* d_out, int out_size) {
    const float* self_v = (const float*)d_in[0];
    const float* nv     = (const float*)d_in[1];
    const float* rel    = (const float*)d_in[2];
    const float* ue     = (const float*)d_in[3];
    const float* W1     = (const float*)d_in[4];
    const float* b1     = (const float*)d_in[5];
    const float* w2     = (const float*)d_in[6];
    const float* b2     = (const float*)d_in[7];
    float* out = (float*)d_out;

    cudaFuncSetAttribute(agg_kernel, cudaFuncAttributeMaxDynamicSharedMemorySize, SMEM_BYTES);
    agg_kernel<<<B_TOTAL / 8, 128, SMEM_BYTES>>>(self_v, nv, rel, ue, W1, b1, w2, b2, out);
}

// round 3
// speedup vs baseline: 1.2352x; 1.1696x over previous
#include <cuda_runtime.h>
#include <cstdint>

#define B_TOTAL 16384

// One warp == one batch. 256 thr/CTA = 8 batches/CTA, grid = 2048.
// No __syncthreads after W staging; all per-batch work is intra-warp.
__global__ __launch_bounds__(256, 2) void agg_kernel(
    const float* __restrict__ self_v,
    const float* __restrict__ nv,
    const float* __restrict__ rel,
    const float* __restrict__ ue,
    const float* __restrict__ W1,
    const float* __restrict__ b1,
    const float* __restrict__ w2,
    const float* __restrict__ b2,
    float* __restrict__ out)
{
    __shared__ float2 sWp[64 * 32];   // B-frags of W1_lower: [(jt*8+ks)*32 + lane] -> (b0,b1)
    __shared__ float  sWU[64 * 64];   // W1_upper row-major [k][j] (for uep)
    __shared__ float  sEx[8][64];     // per-warp exchange: uep, then e[n]

    const int tid  = threadIdx.x;
    const int warp = tid >> 5;
    const int lane = tid & 31;
    const int g = lane >> 2;          // groupID
    const int q = lane & 3;           // threadID_in_group

    // ---- one-time W staging (only CTA-wide barrier in the kernel) ----
    {
        const float4* src = reinterpret_cast<const float4*>(W1);   // upper 64 rows = 1024 float4
        float4* dst = reinterpret_cast<float4*>(sWU);
        for (int i = tid; i < 1024; i += 256) dst[i] = src[i];
    }
    for (int i = tid; i < 2048; i += 256) {
        int l2 = i & 31, jtks = i >> 5;
        int gg = l2 >> 2, qq = l2 & 3;
        int jt = jtks >> 3, ks = jtks & 7;
        float bb0 = W1[(64 + 8 * ks + qq)     * 64 + 8 * jt + gg];
        float bb1 = W1[(64 + 8 * ks + qq + 4) * 64 + 8 * jt + gg];
        sWp[i] = make_float2(bb0, bb1);
    }
    __syncthreads();

    const int b = blockIdx.x * 8 + warp;
    const float b2v = __ldg(b2);

    // ---- uep[j] = b1[j] + ue[b] @ W1_upper[:,j]  (2 j's per lane, then exchange) ----
    {
        const float* ub = ue + (size_t)b * 64;
        float uev0 = __ldg(ub + lane);
        float uev1 = __ldg(ub + lane + 32);
        float acc0 = __ldg(b1 + lane);
        float acc1 = __ldg(b1 + lane + 32);
#pragma unroll
        for (int k = 0; k < 64; k++) {
            float uk = __shfl_sync(0xffffffffu, (k < 32) ? uev0 : uev1, k & 31);
            acc0 = fmaf(uk, sWU[k * 64 + lane],      acc0);
            acc1 = fmaf(uk, sWU[k * 64 + lane + 32], acc1);
        }
        sEx[warp][lane]      = acc0;
        sEx[warp][lane + 32] = acc1;
    }
    __syncwarp();

    // per-lane uep/w2 for its C-frag columns: j = 8*jt + 2q, 8*jt + 2q + 1
    float uj0[8], uj1[8], w20[8], w21[8];
#pragma unroll
    for (int jt = 0; jt < 8; jt++) {
        uj0[jt] = sEx[warp][8 * jt + 2 * q];
        uj1[jt] = sEx[warp][8 * jt + 2 * q + 1];
        w20[jt] = __ldg(w2 + 8 * jt + 2 * q);
        w21[jt] = __ldg(w2 + 8 * jt + 2 * q + 1);
    }
    __syncwarp();   // uep reads done before sEx is overwritten with e[n]

    // ---- main: per m-tile (16 neighbors): GEMM vs all j, relu·w2 reduce, sigmoid->exp ----
    const float* relb = rel + (size_t)b * 4096;
    float teAcc = 0.f;

#pragma unroll
    for (int mt = 0; mt < 4; mt++) {
        // A-frags straight from gmem (raw fp32 bits as tf32): rel[n][k], rows n0+g / n0+g+8
        uint32_t a[8][4];
#pragma unroll
        for (int ks = 0; ks < 8; ks++) {
            const float* r0 = relb + (mt * 16 + g)     * 64 + 8 * ks;
            const float* r1 = relb + (mt * 16 + g + 8) * 64 + 8 * ks;
            a[ks][0] = __float_as_uint(__ldg(r0 + q));
            a[ks][1] = __float_as_uint(__ldg(r1 + q));
            a[ks][2] = __float_as_uint(__ldg(r0 + q + 4));
            a[ks][3] = __float_as_uint(__ldg(r1 + q + 4));
        }

        float s0 = 0.f, s1 = 0.f;   // score partials for neighbors n0+g, n0+g+8
#pragma unroll
        for (int jt = 0; jt < 8; jt++) {
            float c0 = 0.f, c1 = 0.f, c2 = 0.f, c3 = 0.f;
#pragma unroll
            for (int ks = 0; ks < 8; ks++) {
                float2 bv = sWp[(jt * 8 + ks) * 32 + lane];
                asm volatile(
                    "mma.sync.aligned.m16n8k8.row.col.f32.tf32.tf32.f32 "
                    "{%0,%1,%2,%3}, {%4,%5,%6,%7}, {%8,%9}, {%0,%1,%2,%3};\n"
                    : "+f"(c0), "+f"(c1), "+f"(c2), "+f"(c3)
                    : "r"(a[ks][0]), "r"(a[ks][1]), "r"(a[ks][2]), "r"(a[ks][3]),
                      "r"(__float_as_uint(bv.x)), "r"(__float_as_uint(bv.y)));
            }
            // C frag: c0=(g,2q) c1=(g,2q+1) c2=(g+8,2q) c3=(g+8,2q+1), cols are j
            s0 += fmaxf(c0 + uj0[jt], 0.f) * w20[jt] + fmaxf(c1 + uj1[jt], 0.f) * w21[jt];
            s1 += fmaxf(c2 + uj0[jt], 0.f) * w20[jt] + fmaxf(c3 + uj1[jt], 0.f) * w21[jt];
        }
        // reduce over the 4 q-lanes (j distributed over q)
        s0 += __shfl_xor_sync(0xffffffffu, s0, 1);
        s0 += __shfl_xor_sync(0xffffffffu, s0, 2);
        s1 += __shfl_xor_sync(0xffffffffu, s1, 1);
        s1 += __shfl_xor_sync(0xffffffffu, s1, 2);

        float l0 = 1.f / (1.f + __expf(-(s0 + b2v)));
        float l1 = 1.f / (1.f + __expf(-(s1 + b2v)));
        float e0 = __expf(l0);
        float e1 = __expf(l1);
        teAcc += e0 + e1;
        if (q == 0) {
            sEx[warp][mt * 16 + g]     = e0;
            sEx[warp][mt * 16 + g + 8] = e1;
        }
    }

    // softmax denominator: teAcc identical across q-lanes; sum over g-lanes
    teAcc += __shfl_xor_sync(0xffffffffu, teAcc, 4);
    teAcc += __shfl_xor_sync(0xffffffffu, teAcc, 8);
    teAcc += __shfl_xor_sync(0xffffffffu, teAcc, 16);
    float inv_te = __fdividef(1.f, teAcc);
    __syncwarp();   // e[n] visible warp-wide

    // ---- aggregation: out[64+d] = sum_n e[n]*nv[b][n][d] * inv_te; lane owns d=2l,2l+1 ----
    const float* nvb = nv + (size_t)b * 4096;
    float2 aA = make_float2(0.f, 0.f), aB = make_float2(0.f, 0.f);
#pragma unroll
    for (int n = 0; n < 64; n += 2) {
        float e0 = sEx[warp][n];
        float e1 = sEx[warp][n + 1];
        float2 v0 = __ldg(reinterpret_cast<const float2*>(nvb + n * 64) + lane);
        float2 v1 = __ldg(reinterpret_cast<const float2*>(nvb + (n + 1) * 64) + lane);
        aA.x = fmaf(e0, v0.x, aA.x);  aA.y = fmaf(e0, v0.y, aA.y);
        aB.x = fmaf(e1, v1.x, aB.x);  aB.y = fmaf(e1, v1.y, aB.y);
    }

    float2 sv = __ldg(reinterpret_cast<const float2*>(self_v + (size_t)b * 64) + lane);
    float2* ob = reinterpret_cast<float2*>(out + (size_t)b * 128);
    ob[lane]      = sv;
    ob[32 + lane] = make_float2((aA.x + aB.x) * inv_te, (aA.y + aB.y) * inv_te);
}

extern "C" void kernel_launch(void* const* d_in, const int* in_sizes, int n_in,
                              void* d_out, int out_size) {
    const float* self_v = (const float*)d_in[0];
    const float* nv     = (const float*)d_in[1];
    const float* rel    = (const float*)d_in[2];
    const float* ue     = (const float*)d_in[3];
    const float* W1     = (const float*)d_in[4];
    const float* b1     = (const float*)d_in[5];
    const float* w2     = (const float*)d_in[6];
    const float* b2     = (const float*)d_in[7];
    float* out = (float*)d_out;

    agg_kernel<<<B_TOTAL / 8, 256>>>(self_v, nv, rel, ue, W1, b1, w2, b2, out);
}

// round 4
// speedup vs baseline: 1.3989x; 1.1326x over previous
#include <cuda_runtime.h>
#include <cstdint>

#define B_TOTAL 16384
#define RS 68                // rel row stride (floats); pad kills LDS bank conflicts
#define RELTILE (16 * RS)    // 1088 floats per m-tile buffer

// ---- dynamic smem layout (float offsets) ----
#define OFF_WP   0           // float2[2048]: B-frags of W1_lower  (16 KB)
#define OFF_WU   4096        // float[4096] : W1_upper row-major   (16 KB)
#define OFF_W2   8192        // float[64]
#define OFF_EX   8256        // float[8][64]: per-warp e[n]
#define OFF_UEP  8768        // float[8][64]: per-warp uep[j]
#define OFF_REL  9280        // float[8][2][RELTILE]: per-warp rel double buffer (68 KB)
#define SMEM_FLOATS (OFF_REL + 8 * 2 * RELTILE)
#define SMEM_BYTES  (SMEM_FLOATS * 4)

__device__ __forceinline__ void cp16(float* s, const float* g) {
    uint32_t sa = (uint32_t)__cvta_generic_to_shared(s);
    asm volatile("cp.async.cg.shared.global [%0], [%1], 16;\n" :: "r"(sa), "l"(g));
}
template <int N>
__device__ __forceinline__ void cp_wait() { asm volatile("cp.async.wait_group %0;\n" :: "n"(N)); }

// stage one 16x64 rel m-tile -> buf (row stride RS), per-warp, coalesced 16B chunks
__device__ __forceinline__ void stage_tile(float* buf, const float* __restrict__ src, int lane) {
#pragma unroll
    for (int c = 0; c < 8; c++) {
        int i = lane + c * 32;          // chunk 0..255
        int r = i >> 4, s4 = i & 15;
        cp16(buf + r * RS + s4 * 4, src + r * 64 + s4 * 4);
    }
    asm volatile("cp.async.commit_group;\n");
}

__global__ __launch_bounds__(256, 2) void agg_kernel(
    const float* __restrict__ self_v,
    const float* __restrict__ nv,
    const float* __restrict__ rel,
    const float* __restrict__ ue,
    const float* __restrict__ W1,
    const float* __restrict__ b1,
    const float* __restrict__ w2,
    const float* __restrict__ b2,
    float* __restrict__ out)
{
    extern __shared__ __align__(16) float smem[];
    float2* sWp = reinterpret_cast<float2*>(smem + OFF_WP);
    float*  sWU = smem + OFF_WU;
    float*  sW2 = smem + OFF_W2;

    const int tid  = threadIdx.x;
    const int warp = tid >> 5;
    const int lane = tid & 31;
    const int g = lane >> 2;          // groupID
    const int q = lane & 3;           // threadID_in_group

    float* myEx = smem + OFF_EX  + warp * 64;   // e[n]
    float* myU  = smem + OFF_UEP + warp * 64;   // uep[j]
    float* buf0 = smem + OFF_REL + warp * 2 * RELTILE;
    float* buf1 = buf0 + RELTILE;

    // ---- one-time W staging (only CTA-wide barrier) ----
    {
        const float4* src = reinterpret_cast<const float4*>(W1);   // upper 64 rows
        float4* dst = reinterpret_cast<float4*>(sWU);
        for (int i = tid; i < 1024; i += 256) dst[i] = src[i];
    }
    for (int i = tid; i < 2048; i += 256) {
        int l2 = i & 31, jtks = i >> 5;
        int gg = l2 >> 2, qq = l2 & 3;
        int jt = jtks >> 3, ks = jtks & 7;
        float bb0 = W1[(64 + 8 * ks + qq)     * 64 + 8 * jt + gg];
        float bb1 = W1[(64 + 8 * ks + qq + 4) * 64 + 8 * jt + gg];
        sWp[i] = make_float2(bb0, bb1);
    }
    if (tid < 64) sW2[tid] = __ldg(w2 + tid);
    __syncthreads();

    const int b = blockIdx.x * 8 + warp;
    const float* relb = rel + (size_t)b * 4096;
    const float b2v = __ldg(b2);

    // ---- prologue: prefetch m-tiles 0 and 1 ----
    stage_tile(buf0, relb, lane);
    stage_tile(buf1, relb + 1024, lane);

    // ---- uep[j] = b1[j] + ue[b] @ W1_upper[:,j]  (overlaps cp.async latency) ----
    {
        const float* ub = ue + (size_t)b * 64;
        float uev0 = __ldg(ub + lane);
        float uev1 = __ldg(ub + lane + 32);
        float acc0 = __ldg(b1 + lane);
        float acc1 = __ldg(b1 + lane + 32);
#pragma unroll
        for (int k = 0; k < 64; k++) {
            float uk = __shfl_sync(0xffffffffu, (k < 32) ? uev0 : uev1, k & 31);
            acc0 = fmaf(uk, sWU[k * 64 + lane],      acc0);
            acc1 = fmaf(uk, sWU[k * 64 + lane + 32], acc1);
        }
        myU[lane]      = acc0;
        myU[lane + 32] = acc1;
    }
    __syncwarp();

    // hoist per-lane uep/w2 for C-frag columns j = 8*jt + 2q, +1
    float uj0[8], uj1[8], w20[8], w21[8];
#pragma unroll
    for (int jt = 0; jt < 8; jt++) {
        uj0[jt] = myU[8 * jt + 2 * q];
        uj1[jt] = myU[8 * jt + 2 * q + 1];
        w20[jt] = sW2[8 * jt + 2 * q];
        w21[jt] = sW2[8 * jt + 2 * q + 1];
    }

    // ---- main: 4 m-tiles of 16 neighbors, double-buffered cp.async pipeline ----
    float teAcc = 0.f;
#pragma unroll
    for (int mt = 0; mt < 4; mt++) {
        if (mt < 3) cp_wait<1>(); else cp_wait<0>();
        __syncwarp();

        const float* A = (mt & 1) ? buf1 : buf0;
        // A-frags via conflict-free LDS.32 (bank = (4g+8ks+q) mod 32, bijective)
        uint32_t a[8][4];
#pragma unroll
        for (int ks = 0; ks < 8; ks++) {
            const float* r0 = A + g * RS + 8 * ks;
            const float* r1 = A + (g + 8) * RS + 8 * ks;
            a[ks][0] = __float_as_uint(r0[q]);
            a[ks][1] = __float_as_uint(r1[q]);
            a[ks][2] = __float_as_uint(r0[q + 4]);
            a[ks][3] = __float_as_uint(r1[q + 4]);
        }

        // refill this buffer for m-tile mt+2 (async; lands long after the LDS above)
        if (mt < 2)
            stage_tile((mt & 1) ? buf1 : buf0, relb + (mt + 2) * 1024, lane);

        float s0 = 0.f, s1 = 0.f;   // score partials for neighbors mt*16+g, +8
#pragma unroll
        for (int jt = 0; jt < 8; jt++) {
            float c0 = 0.f, c1 = 0.f, c2 = 0.f, c3 = 0.f;
#pragma unroll
            for (int ks = 0; ks < 8; ks++) {
                float2 bv = sWp[(jt * 8 + ks) * 32 + lane];
                asm volatile(
                    "mma.sync.aligned.m16n8k8.row.col.f32.tf32.tf32.f32 "
                    "{%0,%1,%2,%3}, {%4,%5,%6,%7}, {%8,%9}, {%0,%1,%2,%3};\n"
                    : "+f"(c0), "+f"(c1), "+f"(c2), "+f"(c3)
                    : "r"(a[ks][0]), "r"(a[ks][1]), "r"(a[ks][2]), "r"(a[ks][3]),
                      "r"(__float_as_uint(bv.x)), "r"(__float_as_uint(bv.y)));
            }
            s0 += fmaxf(c0 + uj0[jt], 0.f) * w20[jt] + fmaxf(c1 + uj1[jt], 0.f) * w21[jt];
            s1 += fmaxf(c2 + uj0[jt], 0.f) * w20[jt] + fmaxf(c3 + uj1[jt], 0.f) * w21[jt];
        }
        // reduce over 4 q-lanes (j distributed over q)
        s0 += __shfl_xor_sync(0xffffffffu, s0, 1);
        s0 += __shfl_xor_sync(0xffffffffu, s0, 2);
        s1 += __shfl_xor_sync(0xffffffffu, s1, 1);
        s1 += __shfl_xor_sync(0xffffffffu, s1, 2);

        float e0 = __expf(1.f / (1.f + __expf(-(s0 + b2v))));
        float e1 = __expf(1.f / (1.f + __expf(-(s1 + b2v))));
        teAcc += e0 + e1;
        if (q == 0) {
            myEx[mt * 16 + g]     = e0;
            myEx[mt * 16 + g + 8] = e1;
        }
    }

    // softmax denominator (teAcc identical across q-lanes; sum over g-lanes)
    teAcc += __shfl_xor_sync(0xffffffffu, teAcc, 4);
    teAcc += __shfl_xor_sync(0xffffffffu, teAcc, 8);
    teAcc += __shfl_xor_sync(0xffffffffu, teAcc, 16);
    float inv_te = __fdividef(1.f, teAcc);
    __syncwarp();   // e[n] visible warp-wide

    // ---- aggregation: float4 per lane; halves (even/odd n) combined by shfl ----
    const float* nvb = nv + (size_t)b * 4096;
    const int c4 = lane & 15, half = lane >> 4;
    float4 acc = make_float4(0.f, 0.f, 0.f, 0.f);
#pragma unroll
    for (int i = 0; i < 32; i++) {
        int n = 2 * i + half;
        float e = myEx[n];
        float4 v = __ldg(reinterpret_cast<const float4*>(nvb + n * 64) + c4);
        acc.x = fmaf(e, v.x, acc.x);
        acc.y = fmaf(e, v.y, acc.y);
        acc.z = fmaf(e, v.z, acc.z);
        acc.w = fmaf(e, v.w, acc.w);
    }
    acc.x += __shfl_xor_sync(0xffffffffu, acc.x, 16);
    acc.y += __shfl_xor_sync(0xffffffffu, acc.y, 16);
    acc.z += __shfl_xor_sync(0xffffffffu, acc.z, 16);
    acc.w += __shfl_xor_sync(0xffffffffu, acc.w, 16);

    if (lane < 16) {
        reinterpret_cast<float4*>(out + (size_t)b * 128 + 64)[c4] =
            make_float4(acc.x * inv_te, acc.y * inv_te, acc.z * inv_te, acc.w * inv_te);
    } else {
        float4 sv = __ldg(reinterpret_cast<const float4*>(self_v + (size_t)b * 64) + c4);
        reinterpret_cast<float4*>(out + (size_t)b * 128)[c4] = sv;
    }
}

extern "C" void kernel_launch(void* const* d_in, const int* in_sizes, int n_in,
                              void* d_out, int out_size) {
    const float* self_v = (const float*)d_in[0];
    const float* nv     = (const float*)d_in[1];
    const float* rel    = (const float*)d_in[2];
    const float* ue     = (const float*)d_in[3];
    const float* W1     = (const float*)d_in[4];
    const float* b1     = (const float*)d_in[5];
    const float* w2     = (const float*)d_in[6];
    const float* b2     = (const float*)d_in[7];
    float* out = (float*)d_out;

    cudaFuncSetAttribute(agg_kernel, cudaFuncAttributeMaxDynamicSharedMemorySize, SMEM_BYTES);
    agg_kernel<<<B_TOTAL / 8, 256, SMEM_BYTES>>>(self_v, nv, rel, ue, W1, b1, w2, b2, out);
}

// round 5
// speedup vs baseline: 1.6755x; 1.1977x over previous
#include <cuda_runtime.h>
#include <cstdint>

#define B_TOTAL 16384
#define RS 68                // rel row stride (floats); pad -> conflict-free LDS
#define RELTILE (16 * RS)    // 1088 floats per m-tile buffer

// ---- dynamic smem layout (float offsets), ~54.3 KB total ----
#define OFF_WP   0           // float2[2048]: B-frags of W1_lower  (16 KB)
#define OFF_W2   4096        // float[64]
#define OFF_EX   4160        // float[8][64]: per-warp e[n]
#define OFF_UEP  4672        // float[8][64]: per-warp uep[j]
#define OFF_REL  5184        // float[8][RELTILE]: per-warp rel single buffer (34 KB)
#define SMEM_FLOATS (OFF_REL + 8 * RELTILE)
#define SMEM_BYTES  (SMEM_FLOATS * 4)

__device__ __forceinline__ void cp16(float* s, const float* g) {
    uint32_t sa = (uint32_t)__cvta_generic_to_shared(s);
    asm volatile("cp.async.cg.shared.global [%0], [%1], 16;\n" :: "r"(sa), "l"(g));
}
template <int N>
__device__ __forceinline__ void cp_wait() { asm volatile("cp.async.wait_group %0;\n" :: "n"(N)); }

// stage one 16x64 rel m-tile -> buf (row stride RS), per-warp, coalesced 16B chunks
__device__ __forceinline__ void stage_tile(float* buf, const float* __restrict__ src, int lane) {
#pragma unroll
    for (int c = 0; c < 8; c++) {
        int i = lane + c * 32;          // chunk 0..255
        int r = i >> 4, s4 = i & 15;
        cp16(buf + r * RS + s4 * 4, src + r * 64 + s4 * 4);
    }
    asm volatile("cp.async.commit_group;\n");
}

__global__ __launch_bounds__(256, 3) void agg_kernel(
    const float* __restrict__ self_v,
    const float* __restrict__ nv,
    const float* __restrict__ rel,
    const float* __restrict__ ue,
    const float* __restrict__ W1,
    const float* __restrict__ b1,
    const float* __restrict__ w2,
    const float* __restrict__ b2,
    float* __restrict__ out)
{
    extern __shared__ __align__(16) float smem[];
    float2* sWp = reinterpret_cast<float2*>(smem + OFF_WP);
    float*  sW2 = smem + OFF_W2;

    const int tid  = threadIdx.x;
    const int warp = tid >> 5;
    const int lane = tid & 31;
    const int g = lane >> 2;          // groupID
    const int q = lane & 3;           // threadID_in_group

    float* myEx = smem + OFF_EX  + warp * 64;   // e[n]
    float* myU  = smem + OFF_UEP + warp * 64;   // uep[j]
    float* buf  = smem + OFF_REL + warp * RELTILE;

    // ---- one-time W staging (only CTA-wide barrier) ----
    for (int i = tid; i < 2048; i += 256) {
        int l2 = i & 31, jtks = i >> 5;
        int gg = l2 >> 2, qq = l2 & 3;
        int jt = jtks >> 3, ks = jtks & 7;
        float bb0 = __ldg(W1 + (64 + 8 * ks + qq)     * 64 + 8 * jt + gg);
        float bb1 = __ldg(W1 + (64 + 8 * ks + qq + 4) * 64 + 8 * jt + gg);
        sWp[i] = make_float2(bb0, bb1);
    }
    if (tid < 64) sW2[tid] = __ldg(w2 + tid);
    __syncthreads();

    const int b = blockIdx.x * 8 + warp;
    const float* relb = rel + (size_t)b * 4096;
    const float b2v = __ldg(b2);

    // ---- prologue: prefetch m-tile 0 ----
    stage_tile(buf, relb, lane);

    // ---- uep[j] = b1[j] + ue[b] @ W1_upper[:,j]  (overlaps cp.async; W1 L1-hot) ----
    {
        const float* ub = ue + (size_t)b * 64;
        float uev0 = __ldg(ub + lane);
        float uev1 = __ldg(ub + lane + 32);
        float acc0 = __ldg(b1 + lane);
        float acc1 = __ldg(b1 + lane + 32);
#pragma unroll
        for (int k = 0; k < 64; k++) {
            float uk = __shfl_sync(0xffffffffu, (k < 32) ? uev0 : uev1, k & 31);
            acc0 = fmaf(uk, __ldg(W1 + k * 64 + lane),      acc0);
            acc1 = fmaf(uk, __ldg(W1 + k * 64 + lane + 32), acc1);
        }
        myU[lane]      = acc0;
        myU[lane + 32] = acc1;
    }

    // ---- main: 4 m-tiles of 16 neighbors, single-buffered cp.async (dist 1) ----
    float teAcc = 0.f;
#pragma unroll
    for (int mt = 0; mt < 4; mt++) {
        cp_wait<0>();
        __syncwarp();

        // A-frags via conflict-free LDS.32 (bank = (4g+8ks+q) mod 32, bijective)
        uint32_t a[8][4];
#pragma unroll
        for (int ks = 0; ks < 8; ks++) {
            const float* r0 = buf + g * RS + 8 * ks;
            const float* r1 = buf + (g + 8) * RS + 8 * ks;
            a[ks][0] = __float_as_uint(r0[q]);
            a[ks][1] = __float_as_uint(r1[q]);
            a[ks][2] = __float_as_uint(r0[q + 4]);
            a[ks][3] = __float_as_uint(r1[q + 4]);
        }

        // restage this buffer for the next m-tile (async; lands much later)
        if (mt < 3) stage_tile(buf, relb + (mt + 1) * 1024, lane);

        float s0 = 0.f, s1 = 0.f;   // score partials for neighbors mt*16+g, +8
#pragma unroll
        for (int jt = 0; jt < 8; jt++) {
            float c0 = 0.f, c1 = 0.f, c2 = 0.f, c3 = 0.f;
#pragma unroll
            for (int ks = 0; ks < 8; ks++) {
                float2 bv = sWp[(jt * 8 + ks) * 32 + lane];
                asm volatile(
                    "mma.sync.aligned.m16n8k8.row.col.f32.tf32.tf32.f32 "
                    "{%0,%1,%2,%3}, {%4,%5,%6,%7}, {%8,%9}, {%0,%1,%2,%3};\n"
                    : "+f"(c0), "+f"(c1), "+f"(c2), "+f"(c3)
                    : "r"(a[ks][0]), "r"(a[ks][1]), "r"(a[ks][2]), "r"(a[ks][3]),
                      "r"(__float_as_uint(bv.x)), "r"(__float_as_uint(bv.y)));
            }
            // C frag cols j = 8*jt + 2q, +1; uep/w2 from smem (broadcast LDS)
            float u0 = myU[8 * jt + 2 * q],     u1 = myU[8 * jt + 2 * q + 1];
            float v0 = sW2[8 * jt + 2 * q],     v1 = sW2[8 * jt + 2 * q + 1];
            s0 += fmaxf(c0 + u0, 0.f) * v0 + fmaxf(c1 + u1, 0.f) * v1;
            s1 += fmaxf(c2 + u0, 0.f) * v0 + fmaxf(c3 + u1, 0.f) * v1;
        }
        // reduce over 4 q-lanes (j distributed over q)
        s0 += __shfl_xor_sync(0xffffffffu, s0, 1);
        s0 += __shfl_xor_sync(0xffffffffu, s0, 2);
        s1 += __shfl_xor_sync(0xffffffffu, s1, 1);
        s1 += __shfl_xor_sync(0xffffffffu, s1, 2);

        float e0 = __expf(1.f / (1.f + __expf(-(s0 + b2v))));
        float e1 = __expf(1.f / (1.f + __expf(-(s1 + b2v))));
        teAcc += e0 + e1;
        if (q == 0) {
            myEx[mt * 16 + g]     = e0;
            myEx[mt * 16 + g + 8] = e1;
        }
    }

    // softmax denominator (teAcc identical across q-lanes; sum over g-lanes)
    teAcc += __shfl_xor_sync(0xffffffffu, teAcc, 4);
    teAcc += __shfl_xor_sync(0xffffffffu, teAcc, 8);
    teAcc += __shfl_xor_sync(0xffffffffu, teAcc, 16);
    float inv_te = __fdividef(1.f, teAcc);
    __syncwarp();   // e[n] visible warp-wide

    // ---- aggregation: float4 per lane; halves (even/odd n) combined by shfl ----
    const float* nvb = nv + (size_t)b * 4096;
    const int c4 = lane & 15, half = lane >> 4;
    float4 acc = make_float4(0.f, 0.f, 0.f, 0.f);
#pragma unroll
    for (int i = 0; i < 32; i++) {
        int n = 2 * i + half;
        float e = myEx[n];
        float4 v = __ldg(reinterpret_cast<const float4*>(nvb + n * 64) + c4);
        acc.x = fmaf(e, v.x, acc.x);
        acc.y = fmaf(e, v.y, acc.y);
        acc.z = fmaf(e, v.z, acc.z);
        acc.w = fmaf(e, v.w, acc.w);
    }
    acc.x += __shfl_xor_sync(0xffffffffu, acc.x, 16);
    acc.y += __shfl_xor_sync(0xffffffffu, acc.y, 16);
    acc.z += __shfl_xor_sync(0xffffffffu, acc.z, 16);
    acc.w += __shfl_xor_sync(0xffffffffu, acc.w, 16);

    if (lane < 16) {
        reinterpret_cast<float4*>(out + (size_t)b * 128 + 64)[c4] =
            make_float4(acc.x * inv_te, acc.y * inv_te, acc.z * inv_te, acc.w * inv_te);
    } else {
        float4 sv = __ldg(reinterpret_cast<const float4*>(self_v + (size_t)b * 64) + c4);
        reinterpret_cast<float4*>(out + (size_t)b * 128)[c4] = sv;
    }
}

extern "C" void kernel_launch(void* const* d_in, const int* in_sizes, int n_in,
                              void* d_out, int out_size) {
    const float* self_v = (const float*)d_in[0];
    const float* nv     = (const float*)d_in[1];
    const float* rel    = (const float*)d_in[2];
    const float* ue     = (const float*)d_in[3];
    const float* W1     = (const float*)d_in[4];
    const float* b1     = (const float*)d_in[5];
    const float* w2     = (const float*)d_in[6];
    const float* b2     = (const float*)d_in[7];
    float* out = (float*)d_out;

    cudaFuncSetAttribute(agg_kernel, cudaFuncAttributeMaxDynamicSharedMemorySize, SMEM_BYTES);
    agg_kernel<<<B_TOTAL / 8, 256, SMEM_BYTES>>>(self_v, nv, rel, ue, W1, b1, w2, b2, out);
}